// round 14
// baseline (speedup 1.0000x reference)
#include <cuda_runtime.h>

// SConv2d majority-gate conv, s-domain math, packed f32x2 (2 px/thread).
// R12: (a) weights in __constant__ (device-packed + memcpyToSymbolAsync D2D)
//          -> warp-uniform LDC on the constant port, off the L1tex path;
//      (b) g_xW precomputed 3-pair windows (32B entries): 2 LDG per
//          channel-row instead of 3;
//      (c) __launch_bounds__(192,5) for a 5th resident block.

#define C_IN 27
#define NOC 27
#define HH 32
#define WW 32
#define PR 34                      // padded rows: gh = -1..32
#define NW2 16                     // pair-columns per row
#define OCG 3
#define NPAIR 64                   // pixel pairs per block (4 rows x 16)
#define NTHR (NPAIR * 3)           // 192
#define NWEL (NOC * C_IN * 9)      // 6561
#define NENT (8 * C_IN * PR * NW2) // 117504 window entries
#define XWBLK ((NENT + 255) / 256) // 459
#define WBLK  ((NWEL + 255) / 256) // 26

typedef unsigned long long u64;

// window entries: 4 u64 stride (32B): {x[m-1],x[m]}, {x[m],x[m+1]}, {x[m+1],x[m+2]}, pad
__device__ __align__(16) u64 g_xW[NENT * 4];
__device__ __align__(16) u64 g_wp[NWEL];        // packed {w/2,w/2}, tight
__constant__ __align__(16) u64 c_wp[NWEL];      // 52.5 KB

__device__ __forceinline__ u64 pk2(float lo, float hi) {
    u64 r; asm("mov.b64 %0,{%1,%2};" : "=l"(r) : "f"(lo), "f"(hi)); return r;
}
__device__ __forceinline__ void upk2(u64 v, float& lo, float& hi) {
    asm("mov.b64 {%0,%1},%2;" : "=f"(lo), "=f"(hi) : "l"(v));
}
__device__ __forceinline__ u64 ffma2(u64 a, u64 b, u64 c) {
    u64 d; asm("fma.rn.f32x2 %0,%1,%2,%3;" : "=l"(d) : "l"(a), "l"(b), "l"(c)); return d;
}
__device__ __forceinline__ u64 fmul2(u64 a, u64 b) {
    u64 d; asm("mul.rn.f32x2 %0,%1,%2;" : "=l"(d) : "l"(a), "l"(b)); return d;
}
__device__ __forceinline__ u64 fadd2(u64 a, u64 b) {
    u64 d; asm("add.rn.f32x2 %0,%1,%2;" : "=l"(d) : "l"(a), "l"(b)); return d;
}
__device__ __forceinline__ u64 maj3s2(u64 a, u64 b, u64 c, u64 NEG2) {
    u64 p = fmul2(a, b);
    u64 t = fadd2(a, b);
    u64 q = ffma2(NEG2, p, t);     // a+b-2ab
    return ffma2(q, c, p);         // ab + (a+b-2ab)c
}

// ---- fused prep: window triples + packed weights ---------------------------
__global__ __launch_bounds__(256) void prep_kernel(const float* __restrict__ x,
                                                   const float* __restrict__ w) {
    int bid = blockIdx.x;
    if (bid < XWBLK) {
        int t = bid * 256 + threadIdx.x;
        if (t >= NENT) return;
        int w2 = t & (NW2 - 1);
        int r  = t >> 4;               // padded row id: (n*27+c)*34 + hp
        int hp = r % PR;
        int nc = r / PR;
        int gh = hp - 1;
        bool rowok = (unsigned)gh < (unsigned)HH;
        const float* xb = x + (size_t)nc * (HH * WW) + gh * WW;
        int m = 2 * w2;
        float v0 = (rowok && m >= 1)      ? xb[m - 1] : -1.0f;
        float v1 = rowok                  ? xb[m]     : -1.0f;
        float v2 = rowok                  ? xb[m + 1] : -1.0f;
        float v3 = (rowok && m + 2 < WW)  ? xb[m + 2] : -1.0f;
        ulonglong2* e = (ulonglong2*)&g_xW[(size_t)t * 4];
        e[0] = make_ulonglong2(pk2(v0, v1), pk2(v1, v2));
        g_xW[(size_t)t * 4 + 2] = pk2(v2, v3);
    } else {
        int e = (bid - XWBLK) * 256 + threadIdx.x;
        if (e >= NWEL) return;
        float v = 0.5f * w[e];
        g_wp[e] = pk2(v, v);           // same linear order as input (oc,c,kh,kw)
    }
}

// ---- main ------------------------------------------------------------------
__global__ __launch_bounds__(NTHR, 5) void sconv_kernel(float* __restrict__ out) {
    __shared__ __align__(16) u64 part[3 * OCG * NPAIR];   // 9*64 u64 = 4608 B

    int b = blockIdx.x;
    int ocg  = b % 9;              // 0..8  -> oc group
    int tile = (b / 9) & 7;        // 0..7  -> 4-row tile
    int n    = b / 72;             // 0..7
    int h0 = tile * 4;
    int oc0 = ocg * OCG;

    int tid = threadIdx.x;
    int pp  = tid & (NPAIR - 1);   // 0..63
    int cg  = tid >> 6;            // 0..2 (9 channels each)
    int wc2 = pp & 15;
    int hl  = pp >> 4;             // 0..3
    int h   = h0 + hl;

    const u64 HALF2 = pk2(0.5f, 0.5f);
    const u64 NEG2  = pk2(-2.0f, -2.0f);

    int c0 = 9 * cg;
    // u64 base into g_xW for (n, c0, padded row h, wc2); per (cl,kh): +(cl*34+kh)*64
    const u64* xwb = g_xW + (((size_t)(n * C_IN + c0) * PR + h) * NW2 + wc2) * 4;
    // constant weight base for (oc0, c0)
    const int wbase = (oc0 * C_IN + c0) * 9;

    u64 ub[OCG][3];
    u64 vtmp[OCG][3];

    #pragma unroll
    for (int g3 = 0; g3 < 3; g3++) {           // three 3-channel subgroups
        #pragma unroll
        for (int cl = 0; cl < 3; cl++) {
            int cc = g3 * 3 + cl;
            u64 xp[9];
            #pragma unroll
            for (int kh = 0; kh < 3; kh++) {
                const u64* e = xwb + ((size_t)cc * PR + kh) * (NW2 * 4);
                ulonglong2 ab = __ldg((const ulonglong2*)e);
                xp[kh * 3 + 0] = ab.x;                 // {x[w-1], x[w]}
                xp[kh * 3 + 1] = ab.y;                 // {x[w],   x[w+1]}
                xp[kh * 3 + 2] = __ldg(e + 2);         // {x[w+1], x[w+2]}
            }
            #pragma unroll
            for (int o = 0; o < OCG; o++) {
                const u64* wk = &c_wp[wbase + (o * C_IN + cc) * 9];
                u64 rkh[3];
                #pragma unroll
                for (int kh = 0; kh < 3; kh++) {
                    u64 s0 = ffma2(xp[kh * 3 + 0], wk[kh * 3 + 0], HALF2);
                    u64 s1 = ffma2(xp[kh * 3 + 1], wk[kh * 3 + 1], HALF2);
                    u64 s2 = ffma2(xp[kh * 3 + 2], wk[kh * 3 + 2], HALF2);
                    rkh[kh] = maj3s2(s0, s1, s2, NEG2);
                }
                vtmp[o][cl] = maj3s2(rkh[0], rkh[1], rkh[2], NEG2);
            }
        }
        #pragma unroll
        for (int o = 0; o < OCG; o++)
            ub[o][g3] = maj3s2(vtmp[o][0], vtmp[o][1], vtmp[o][2], NEG2);
    }

    // t-subtree root per oc for this cg
    u64 tp[OCG];
    #pragma unroll
    for (int o = 0; o < OCG; o++)
        tp[o] = maj3s2(ub[o][0], ub[o][1], ub[o][2], NEG2);

    // ---- exchange across the 3 cg groups
    #pragma unroll
    for (int o = 0; o < OCG; o++)
        part[(cg * OCG + o) * NPAIR + pp] = tp[o];
    __syncthreads();

    // thread (pp, cg) finalizes oc = cg
    u64 t0 = part[(0 * OCG + cg) * NPAIR + pp];
    u64 t1 = part[(1 * OCG + cg) * NPAIR + pp];
    u64 t2 = part[(2 * OCG + cg) * NPAIR + pp];
    u64 rr = maj3s2(t0, t1, t2, NEG2);
    u64 y2 = ffma2(pk2(2.0f, 2.0f), rr, pk2(-1.0f, -1.0f));
    float ylo, yhi;
    upk2(y2, ylo, yhi);

    float2* op = (float2*)&out[(((size_t)n * NOC + (oc0 + cg)) * HH + h) * WW + 2 * wc2];
    *op = make_float2(ylo, yhi);
}

extern "C" void kernel_launch(void* const* d_in, const int* in_sizes, int n_in,
                              void* d_out, int out_size) {
    const float* x = (const float*)d_in[0];     // (8,27,32,32) fp32
    const float* w = (const float*)d_in[1];     // (27,27,3,3) fp32
    float* out = (float*)d_out;                 // (8,27,32,32) fp32

    prep_kernel<<<XWBLK + WBLK, 256>>>(x, w);   // 485 blocks

    // copy packed weights into constant bank (D2D memcpy node, capturable)
    void* wp_dev = nullptr;
    cudaGetSymbolAddress(&wp_dev, g_wp);
    cudaMemcpyToSymbolAsync(c_wp, wp_dev, NWEL * sizeof(u64), 0,
                            cudaMemcpyDeviceToDevice, 0);

    sconv_kernel<<<8 * 8 * 9, NTHR>>>(out);     // 576 blocks x 192 threads
}

// round 15
// speedup vs baseline: 2.0292x; 2.0292x over previous
#include <cuda_runtime.h>

// SConv2d majority-gate conv, s-domain math, packed f32x2 (2 px/thread).
// R14: g_xW precomputed window triples (54 x-LDGs/thread) + weights staged
//      per block into smem (LDS broadcast in loop). Constant-memory path
//      from R12 removed (LDC 8-cyc port floor was the regression cause).

#define C_IN 27
#define NOC 27
#define HH 32
#define WW 32
#define PR 34                      // padded rows: gh = -1..32
#define NW2 16                     // pair-columns per row
#define OCG 3
#define NPAIR 64                   // pixel pairs per block (4 rows x 16)
#define NTHR (NPAIR * 3)           // 192
#define NWEL (NOC * C_IN * 9)      // 6561
#define NENT (8 * C_IN * PR * NW2) // 117504 window entries
#define XWBLK ((NENT + 255) / 256) // 459
#define WBLK  ((NWEL + 255) / 256) // 26

typedef unsigned long long u64;

// window entries: 4 u64 stride (32B): {x[m-1],x[m]}, {x[m],x[m+1]}, {x[m+1],x[m+2]}, pad
__device__ __align__(16) u64 g_xW[NENT * 4];
__device__ __align__(16) u64 g_wp[NWEL];        // packed {w/2,w/2}, order (oc,c,k)

__device__ __forceinline__ u64 pk2(float lo, float hi) {
    u64 r; asm("mov.b64 %0,{%1,%2};" : "=l"(r) : "f"(lo), "f"(hi)); return r;
}
__device__ __forceinline__ void upk2(u64 v, float& lo, float& hi) {
    asm("mov.b64 {%0,%1},%2;" : "=f"(lo), "=f"(hi) : "l"(v));
}
__device__ __forceinline__ u64 ffma2(u64 a, u64 b, u64 c) {
    u64 d; asm("fma.rn.f32x2 %0,%1,%2,%3;" : "=l"(d) : "l"(a), "l"(b), "l"(c)); return d;
}
__device__ __forceinline__ u64 fmul2(u64 a, u64 b) {
    u64 d; asm("mul.rn.f32x2 %0,%1,%2;" : "=l"(d) : "l"(a), "l"(b)); return d;
}
__device__ __forceinline__ u64 fadd2(u64 a, u64 b) {
    u64 d; asm("add.rn.f32x2 %0,%1,%2;" : "=l"(d) : "l"(a), "l"(b)); return d;
}
__device__ __forceinline__ u64 maj3s2(u64 a, u64 b, u64 c, u64 NEG2) {
    u64 p = fmul2(a, b);
    u64 t = fadd2(a, b);
    u64 q = ffma2(NEG2, p, t);     // a+b-2ab
    return ffma2(q, c, p);         // ab + (a+b-2ab)c
}

// ---- fused prep: window triples + packed weights ---------------------------
__global__ __launch_bounds__(256) void prep_kernel(const float* __restrict__ x,
                                                   const float* __restrict__ w) {
    int bid = blockIdx.x;
    if (bid < XWBLK) {
        int t = bid * 256 + threadIdx.x;
        if (t >= NENT) return;
        int w2 = t & (NW2 - 1);
        int r  = t >> 4;               // padded row id: (n*27+c)*34 + hp
        int hp = r % PR;
        int nc = r / PR;
        int gh = hp - 1;
        bool rowok = (unsigned)gh < (unsigned)HH;
        const float* xb = x + (size_t)nc * (HH * WW) + gh * WW;
        int m = 2 * w2;
        float v0 = (rowok && m >= 1)      ? xb[m - 1] : -1.0f;
        float v1 = rowok                  ? xb[m]     : -1.0f;
        float v2 = rowok                  ? xb[m + 1] : -1.0f;
        float v3 = (rowok && m + 2 < WW)  ? xb[m + 2] : -1.0f;
        ulonglong2* e = (ulonglong2*)&g_xW[(size_t)t * 4];
        e[0] = make_ulonglong2(pk2(v0, v1), pk2(v1, v2));
        g_xW[(size_t)t * 4 + 2] = pk2(v2, v3);
    } else {
        int e = (bid - XWBLK) * 256 + threadIdx.x;
        if (e >= NWEL) return;
        float v = 0.5f * w[e];
        g_wp[e] = pk2(v, v);           // same linear order as input (oc,c,kh,kw)
    }
}

// ---- main ------------------------------------------------------------------
__global__ __launch_bounds__(NTHR, 5) void sconv_kernel(float* __restrict__ out) {
    __shared__ __align__(16) u64 wsm[OCG * C_IN * 9];     // 729 u64 = 5832 B
    __shared__ __align__(16) u64 part[3 * OCG * NPAIR];   // 576 u64 = 4608 B

    int b = blockIdx.x;
    int ocg  = b % 9;              // 0..8  -> oc group
    int tile = (b / 9) & 7;        // 0..7  -> 4-row tile
    int n    = b / 72;             // 0..7
    int h0 = tile * 4;
    int oc0 = ocg * OCG;

    int tid = threadIdx.x;
    int pp  = tid & (NPAIR - 1);   // 0..63
    int cg  = tid >> 6;            // 0..2 (9 channels each)
    int wc2 = pp & 15;
    int hl  = pp >> 4;             // 0..3
    int h   = h0 + hl;

    // stage this block's 3 ocs of packed weights (contiguous in g_wp)
    const u64* wsrc = g_wp + oc0 * (C_IN * 9);
    #pragma unroll
    for (int i = 0; i < 4; i++) {
        int idx = tid + i * NTHR;
        if (idx < OCG * C_IN * 9)
            wsm[idx] = __ldg(wsrc + idx);
    }
    __syncthreads();

    const u64 HALF2 = pk2(0.5f, 0.5f);
    const u64 NEG2  = pk2(-2.0f, -2.0f);

    int c0 = 9 * cg;
    // u64 base into g_xW for (n, c0, padded row h, wc2)
    const u64* xwb = g_xW + (((size_t)(n * C_IN + c0) * PR + h) * NW2 + wc2) * 4;

    u64 ub[OCG][3];
    u64 vtmp[OCG][3];

    #pragma unroll
    for (int g3 = 0; g3 < 3; g3++) {           // three 3-channel subgroups
        #pragma unroll
        for (int cl = 0; cl < 3; cl++) {
            int cc = g3 * 3 + cl;
            u64 xp[9];
            #pragma unroll
            for (int kh = 0; kh < 3; kh++) {
                const u64* e = xwb + ((size_t)cc * PR + kh) * (NW2 * 4);
                ulonglong2 ab = __ldg((const ulonglong2*)e);
                xp[kh * 3 + 0] = ab.x;                 // {x[w-1], x[w]}
                xp[kh * 3 + 1] = ab.y;                 // {x[w],   x[w+1]}
                xp[kh * 3 + 2] = __ldg(e + 2);         // {x[w+1], x[w+2]}
            }
            #pragma unroll
            for (int o = 0; o < OCG; o++) {
                const u64* wk = &wsm[(o * C_IN + (c0 + cc)) * 9];  // warp-uniform LDS
                u64 rkh[3];
                #pragma unroll
                for (int kh = 0; kh < 3; kh++) {
                    u64 s0 = ffma2(xp[kh * 3 + 0], wk[kh * 3 + 0], HALF2);
                    u64 s1 = ffma2(xp[kh * 3 + 1], wk[kh * 3 + 1], HALF2);
                    u64 s2 = ffma2(xp[kh * 3 + 2], wk[kh * 3 + 2], HALF2);
                    rkh[kh] = maj3s2(s0, s1, s2, NEG2);
                }
                vtmp[o][cl] = maj3s2(rkh[0], rkh[1], rkh[2], NEG2);
            }
        }
        #pragma unroll
        for (int o = 0; o < OCG; o++)
            ub[o][g3] = maj3s2(vtmp[o][0], vtmp[o][1], vtmp[o][2], NEG2);
    }

    // t-subtree root per oc for this cg
    u64 tp[OCG];
    #pragma unroll
    for (int o = 0; o < OCG; o++)
        tp[o] = maj3s2(ub[o][0], ub[o][1], ub[o][2], NEG2);

    // ---- exchange across the 3 cg groups
    #pragma unroll
    for (int o = 0; o < OCG; o++)
        part[(cg * OCG + o) * NPAIR + pp] = tp[o];
    __syncthreads();

    // thread (pp, cg) finalizes oc = cg
    u64 t0 = part[(0 * OCG + cg) * NPAIR + pp];
    u64 t1 = part[(1 * OCG + cg) * NPAIR + pp];
    u64 t2 = part[(2 * OCG + cg) * NPAIR + pp];
    u64 rr = maj3s2(t0, t1, t2, NEG2);
    u64 y2 = ffma2(pk2(2.0f, 2.0f), rr, pk2(-1.0f, -1.0f));
    float ylo, yhi;
    upk2(y2, ylo, yhi);

    float2* op = (float2*)&out[(((size_t)n * NOC + (oc0 + cg)) * HH + h) * WW + 2 * wc2];
    *op = make_float2(ylo, yhi);
}

extern "C" void kernel_launch(void* const* d_in, const int* in_sizes, int n_in,
                              void* d_out, int out_size) {
    const float* x = (const float*)d_in[0];     // (8,27,32,32) fp32
    const float* w = (const float*)d_in[1];     // (27,27,3,3) fp32
    float* out = (float*)d_out;                 // (8,27,32,32) fp32

    prep_kernel<<<XWBLK + WBLK, 256>>>(x, w);   // 485 blocks
    sconv_kernel<<<8 * 8 * 9, NTHR>>>(out);     // 576 blocks x 192 threads
}